// round 1
// baseline (speedup 1.0000x reference)
#include <cuda_runtime.h>

// LSTM: B=128, T=365, D=32, H=512. out[b,t,:] = h_t (fp32).
// Strategy: 365 sequential step kernels (graph nodes). Each step fuses
//   z = h_{t-1}@Wh + x_t@Wx + b  (M=128, N=2048, K=512+32)
// with the gate nonlinearities and c/h update. h-state lives in d_out itself;
// c-state is a __device__ scratch array re-zeroed at the start of each launch.

#define B_  128
#define T_  365
#define D_  32
#define H_  512
#define G4  2048          // 4*H
#define BM  64            // batch rows per block
#define JN  8             // hidden units per block (x4 gates = 32 N-cols)
#define BK  32            // K chunk
#define NCHUNK 17         // 16 chunks of Wh (K=512) + 1 chunk of Wx (K=32)

__device__ float g_c[B_ * H_];   // cell state scratch
__device__ float g_h0[H_];       // never written -> stays zero (h_{-1})

__global__ void zero_c_kernel() {
    int i = blockIdx.x * blockDim.x + threadIdx.x;
    if (i < B_ * H_) g_c[i] = 0.0f;
}

__device__ __forceinline__ float fast_sigmoid(float z) {
    return 1.0f / (1.0f + __expf(-z));
}
__device__ __forceinline__ float fast_tanh(float z) {
    // tanh(z) = 1 - 2/(exp(2z)+1); accurate to ~1e-6 with __expf
    return 1.0f - 2.0f / (__expf(2.0f * z) + 1.0f);
}

// grid: (H/JN = 64, B/BM = 2), 256 threads
__global__ __launch_bounds__(256) void lstm_step_kernel(
    const float* __restrict__ x,    // [B, T, D]
    const float* __restrict__ Wx,   // [D, 4H]
    const float* __restrict__ Wh,   // [H, 4H]
    const float* __restrict__ bias, // [4H]
    float* __restrict__ out,        // [B, T, H]
    const float* __restrict__ hprev_in, // out + (t-1)*H   (ignored when t==0)
    int hstride,                    // T*H, or 0 when t==0 (use g_h0)
    int t)
{
    __shared__ float sh_a[BM][BK + 1];  // [m][k], +1 pad
    __shared__ float sh_w[BK][4 * JN];  // [k][j*4 + gate]  (gate: 0=i,1=f,2=g,3=o)

    const int tid = threadIdx.x;
    const int tm  = tid & 31;   // 32 m-positions, 2 rows each
    const int tj  = tid >> 5;   // 8 hidden-unit positions
    const int j0  = blockIdx.x * JN;
    const int m0  = blockIdx.y * BM;

    const float* hprev = (hstride == 0) ? g_h0 : hprev_in;

    float acc[2][4] = {};

    for (int c = 0; c < NCHUNK; ++c) {
        const bool isx = (c == NCHUNK - 1);
        const int kbase = c * BK;

        // ---- load A tile: [BM x BK], coalesced along k ----
        #pragma unroll
        for (int i = 0; i < (BM * BK) / 256; ++i) {   // 8 iters
            int idx = i * 256 + tid;
            int k = idx & (BK - 1);
            int m = idx >> 5;
            float v;
            if (isx) v = x[(size_t)(m0 + m) * (T_ * D_) + (size_t)t * D_ + k];
            else     v = hprev[(size_t)(m0 + m) * hstride + kbase + k];
            sh_a[m][k] = v;
        }

        // ---- load W tile: [BK x (JN*4)], interleaved [k][j*4+g] ----
        #pragma unroll
        for (int i = 0; i < (BK * 4 * JN) / 256; ++i) {  // 4 iters
            int idx = i * 256 + tid;
            int k = idx >> 5;
            int r = idx & 31;          // r = j*4 + g
            int g = r & 3;
            int j = r >> 2;
            int col = g * H_ + j0 + j;
            float v = isx ? Wx[(size_t)k * G4 + col]
                          : Wh[(size_t)(kbase + k) * G4 + col];
            sh_w[k][r] = v;
        }
        __syncthreads();

        // ---- compute: 8 FFMA per kk per thread ----
        #pragma unroll
        for (int kk = 0; kk < BK; ++kk) {
            float a0 = sh_a[tm * 2 + 0][kk];
            float a1 = sh_a[tm * 2 + 1][kk];
            float4 w = *reinterpret_cast<const float4*>(&sh_w[kk][tj * 4]);
            acc[0][0] += a0 * w.x;  acc[0][1] += a0 * w.y;
            acc[0][2] += a0 * w.z;  acc[0][3] += a0 * w.w;
            acc[1][0] += a1 * w.x;  acc[1][1] += a1 * w.y;
            acc[1][2] += a1 * w.z;  acc[1][3] += a1 * w.w;
        }
        __syncthreads();
    }

    // ---- epilogue: gates + state update ----
    const int j = j0 + tj;
    const float bi = bias[0 * H_ + j];
    const float bf = bias[1 * H_ + j];
    const float bg = bias[2 * H_ + j];
    const float bo = bias[3 * H_ + j];

    #pragma unroll
    for (int r = 0; r < 2; ++r) {
        int m = m0 + tm * 2 + r;
        float ig = fast_sigmoid(acc[r][0] + bi);
        float fg = fast_sigmoid(acc[r][1] + bf);
        float gg = fast_tanh   (acc[r][2] + bg);
        float og = fast_sigmoid(acc[r][3] + bo);

        float cold = g_c[m * H_ + j];
        float cnew = fg * cold + ig * gg;
        g_c[m * H_ + j] = cnew;
        out[(size_t)m * (T_ * H_) + (size_t)t * H_ + j] = og * fast_tanh(cnew);
    }
}

extern "C" void kernel_launch(void* const* d_in, const int* in_sizes, int n_in,
                              void* d_out, int out_size) {
    const float* x  = (const float*)d_in[0];   // [128,365,32]
    const float* Wx = (const float*)d_in[1];   // [32,2048]
    const float* Wh = (const float*)d_in[2];   // [512,2048]
    const float* b  = (const float*)d_in[3];   // [2048]
    float* out = (float*)d_out;                // [128,365,512]

    zero_c_kernel<<<(B_ * H_ + 255) / 256, 256>>>();

    dim3 grid(H_ / JN, B_ / BM);  // (64, 2) = 128 blocks
    for (int t = 0; t < T_; ++t) {
        const float* hp = (t == 0) ? nullptr : out + (size_t)(t - 1) * H_;
        int hs = (t == 0) ? 0 : T_ * H_;
        lstm_step_kernel<<<grid, 256>>>(x, Wx, Wh, b, out, hp, hs, t);
    }
}

// round 2
// speedup vs baseline: 1.9203x; 1.9203x over previous
#include <cuda_runtime.h>

// Persistent LSTM: B=128, T=365, D=32, H=512, fp32, out[b,t,:]=h_t.
// One launch. 128 CTAs x 128 threads, CTA tile = 32 batch-rows x 16 hidden
// units (x4 gates). W slice (139 KB) stays resident in smem all 365 steps;
// cell state lives in registers; h is exchanged via d_out + a software grid
// barrier. Inner product uses packed fma.rn.f32x2 (gate pairs (i,f),(g,o)).

#define B_   128
#define T_   365
#define D_   32
#define H_   512
#define G4   2048
#define KTOT 544            // 512 (Wh) + 32 (Wx)
#define NCTA 128
#define NTHR 128
#define UPB  16             // hidden units per CTA
#define MPB  32             // batch rows per CTA
#define APITCH 545          // 544 + 1 (bank-conflict-free scalar reads)

#define SW2_F2 (KTOT * UPB * 2)                       // float2 elements of W
#define SMEM_BYTES (SW2_F2 * 8 + MPB * APITCH * 4)    // 139264 + 69760 = 209024

__device__ unsigned int g_arrive;
__device__ volatile unsigned int g_release;

__global__ void init_barrier_kernel() { g_arrive = 0u; g_release = 0u; }

__device__ __forceinline__ unsigned long long pack2(float v) {
    unsigned long long r;
    asm("mov.b64 %0, {%1, %1};" : "=l"(r) : "f"(v));
    return r;
}
__device__ __forceinline__ void ffma2(unsigned long long& d,
                                      unsigned long long a,
                                      unsigned long long b) {
    asm("fma.rn.f32x2 %0, %1, %2, %0;" : "+l"(d) : "l"(a), "l"(b));
}
__device__ __forceinline__ void unpack2(unsigned long long v, float& lo, float& hi) {
    asm("mov.b64 {%0, %1}, %2;" : "=f"(lo), "=f"(hi) : "l"(v));
}
__device__ __forceinline__ float fsig(float z) {
    return 1.0f / (1.0f + __expf(-z));
}
__device__ __forceinline__ float ftanh(float z) {
    return 1.0f - 2.0f / (__expf(2.0f * z) + 1.0f);
}

__global__ __launch_bounds__(NTHR, 1) void lstm_persistent(
    const float* __restrict__ x,    // [B,T,D]
    const float* __restrict__ Wx,   // [D,4H]
    const float* __restrict__ Wh,   // [H,4H]
    const float* __restrict__ bias, // [4H]
    float* __restrict__ out)        // [B,T,H]
{
    extern __shared__ float smem[];
    float2* sW2 = (float2*)smem;                 // [KTOT][UPB][2] pairs (i,f),(g,o)
    float*  sA  = smem + SW2_F2 * 2;             // [MPB][APITCH]

    const int tid  = threadIdx.x;
    const int mIdx = tid & 7;                    // 8 m-groups of 4 rows
    const int u    = tid >> 3;                   // 16 unit slots
    const int cta  = blockIdx.x;
    const int ub   = cta & 31;                   // 32 unit-blocks
    const int mb   = cta >> 5;                   // 4 m-blocks
    const int j0   = ub * UPB;
    const int m0   = mb * MPB;
    const int j    = j0 + u;

    // ---- prologue: stage W slice into smem (once for all 365 steps) ----
    for (int idx = tid; idx < KTOT * UPB; idx += NTHR) {
        int k  = idx >> 4;
        int uu = idx & 15;
        int col = j0 + uu;
        const float* Wrow = (k < H_) ? (Wh + (size_t)k * G4)
                                     : (Wx + (size_t)(k - H_) * G4);
        sW2[k * (UPB * 2) + uu * 2 + 0] = make_float2(Wrow[0 * H_ + col], Wrow[1 * H_ + col]);
        sW2[k * (UPB * 2) + uu * 2 + 1] = make_float2(Wrow[2 * H_ + col], Wrow[3 * H_ + col]);
    }
    const float bi = bias[0 * H_ + j];
    const float bf = bias[1 * H_ + j];
    const float bg = bias[2 * H_ + j];
    const float bo = bias[3 * H_ + j];
    float c_reg[4] = {0.f, 0.f, 0.f, 0.f};
    __syncthreads();

    for (int t = 0; t < T_; ++t) {
        // ---- load A tile: [32 rows][h(512) | x(32)] into sA ----
        {
            const float* hbase = out + (size_t)(t - 1) * H_;
            for (int idx = tid; idx < MPB * 136; idx += NTHR) {
                int m = idx / 136;
                int q = idx - m * 136;
                float4 v;
                if (q < 128) {
                    if (t == 0) v = make_float4(0.f, 0.f, 0.f, 0.f);
                    else v = *(const float4*)(hbase +
                             (size_t)(m0 + m) * ((size_t)T_ * H_) + q * 4);
                } else {
                    v = *(const float4*)(x + (size_t)(m0 + m) * (T_ * D_) +
                                         t * D_ + (q - 128) * 4);
                }
                float* dst = sA + m * APITCH + q * 4;
                dst[0] = v.x; dst[1] = v.y; dst[2] = v.z; dst[3] = v.w;
            }
        }
        __syncthreads();

        // ---- z = [h,x] @ [Wh;Wx] for 4 m-rows x 1 unit x 4 gates ----
        unsigned long long acc[4][2] = {};
        const float* aptr = sA + (mIdx * 4) * APITCH;
        const char*  wbase = (const char*)sW2 + (size_t)u * 16;

        #pragma unroll 4
        for (int k = 0; k < KTOT; ++k) {
            ulonglong2 w = *(const ulonglong2*)(wbase + (size_t)k * (UPB * 2 * 8));
            unsigned long long a0 = pack2(aptr[0 * APITCH + k]);
            unsigned long long a1 = pack2(aptr[1 * APITCH + k]);
            unsigned long long a2 = pack2(aptr[2 * APITCH + k]);
            unsigned long long a3 = pack2(aptr[3 * APITCH + k]);
            ffma2(acc[0][0], a0, w.x); ffma2(acc[0][1], a0, w.y);
            ffma2(acc[1][0], a1, w.x); ffma2(acc[1][1], a1, w.y);
            ffma2(acc[2][0], a2, w.x); ffma2(acc[2][1], a2, w.y);
            ffma2(acc[3][0], a3, w.x); ffma2(acc[3][1], a3, w.y);
        }

        // ---- gates, state update, h writeback ----
        #pragma unroll
        for (int r = 0; r < 4; ++r) {
            float zi, zf, zg, zo;
            unpack2(acc[r][0], zi, zf);
            unpack2(acc[r][1], zg, zo);
            float ig = fsig(zi + bi);
            float fg = fsig(zf + bf);
            float gg = ftanh(zg + bg);
            float og = fsig(zo + bo);
            float cn = fg * c_reg[r] + ig * gg;
            c_reg[r] = cn;
            float h  = og * ftanh(cn);
            out[(size_t)(m0 + mIdx * 4 + r) * ((size_t)T_ * H_) +
                (size_t)t * H_ + j] = h;
        }

        // ---- grid barrier (release h_t to every CTA) ----
        __threadfence();
        __syncthreads();
        if (tid == 0) {
            unsigned prev = atomicAdd(&g_arrive, 1u);
            if (prev == (unsigned)(t + 1) * NCTA - 1u) {
                g_release = (unsigned)(t + 1);
            } else {
                while (g_release < (unsigned)(t + 1)) { __nanosleep(32); }
            }
        }
        __syncthreads();
        __threadfence();
    }
}

extern "C" void kernel_launch(void* const* d_in, const int* in_sizes, int n_in,
                              void* d_out, int out_size) {
    const float* x  = (const float*)d_in[0];
    const float* Wx = (const float*)d_in[1];
    const float* Wh = (const float*)d_in[2];
    const float* b  = (const float*)d_in[3];
    float* out = (float*)d_out;

    static bool attr_set = false;
    if (!attr_set) {
        cudaFuncSetAttribute(lstm_persistent,
                             cudaFuncAttributeMaxDynamicSharedMemorySize,
                             SMEM_BYTES);
        attr_set = true;
    }

    init_barrier_kernel<<<1, 1>>>();
    lstm_persistent<<<NCTA, NTHR, SMEM_BYTES>>>(x, Wx, Wh, b, out);
}

// round 3
// speedup vs baseline: 2.2192x; 1.1557x over previous
#include <cuda_runtime.h>

// Persistent LSTM: B=128, T=365, D=32, H=512, fp32, out[b,t,:]=h_t.
// 128 CTAs x 256 threads, CTA tile = 32 batch-rows x 16 hidden units (x4
// gates). W slice (139 KB) resident in smem for all 365 steps; cell state in
// registers; h exchanged through d_out with a 4x32-CTA group barrier.
// Thread tile: 1 m-row x 2 units; inner product in packed fma.rn.f32x2 with
// gate pairs (i,f),(g,o) -> 4 FFMA2 + 4 other instr per k (fma-issue-bound).

#define B_   128
#define T_   365
#define D_   32
#define H_   512
#define G4   2048
#define KTOT 544            // 512 (Wh) + 32 (Wx)
#define NCTA 128
#define NTHR 256
#define UPB  16             // hidden units per CTA
#define MPB  32             // batch rows per CTA
#define APITCH 545          // bank-conflict-free scalar reads

#define SW_U64 (KTOT * UPB * 2)                      // ulonglong pairs of W
#define SMEM_BYTES (SW_U64 * 8 + MPB * APITCH * 4)   // 139264 + 69760 = 209024

__device__ unsigned int g_arrive[4];
__device__ volatile unsigned int g_release[4];

__global__ void init_barrier_kernel() {
    if (threadIdx.x < 4) { g_arrive[threadIdx.x] = 0u; g_release[threadIdx.x] = 0u; }
}

__device__ __forceinline__ unsigned long long pack2(float v) {
    unsigned long long r;
    asm("mov.b64 %0, {%1, %1};" : "=l"(r) : "f"(v));
    return r;
}
__device__ __forceinline__ void ffma2(unsigned long long& d,
                                      unsigned long long a,
                                      unsigned long long b) {
    asm("fma.rn.f32x2 %0, %1, %2, %0;" : "+l"(d) : "l"(a), "l"(b));
}
__device__ __forceinline__ void unpack2(unsigned long long v, float& lo, float& hi) {
    asm("mov.b64 {%0, %1}, %2;" : "=f"(lo), "=f"(hi) : "l"(v));
}
__device__ __forceinline__ float fsig(float z) {
    return 1.0f / (1.0f + __expf(-z));
}
__device__ __forceinline__ float ftanh(float z) {
    return 1.0f - 2.0f / (__expf(2.0f * z) + 1.0f);
}

__global__ __launch_bounds__(NTHR, 1) void lstm_persistent(
    const float* __restrict__ x,    // [B,T,D]
    const float* __restrict__ Wx,   // [D,4H]
    const float* __restrict__ Wh,   // [H,4H]
    const float* __restrict__ bias, // [4H]
    float* __restrict__ out)        // [B,T,H]
{
    extern __shared__ float smem[];
    unsigned long long* sW = (unsigned long long*)smem;  // [KTOT][UPB][2] pairs
    float* sA = smem + SW_U64 * 2;                       // [MPB][APITCH]

    const int tid = threadIdx.x;
    const int tm  = tid & 31;                 // batch row within tile
    const int tg  = tid >> 5;                 // 0..7 -> unit pair (2tg, 2tg+1)
    const int ub  = blockIdx.x & 31;          // 32 unit-blocks
    const int mb  = blockIdx.x >> 5;          // 4 m-blocks (barrier group)
    const int j0  = ub * UPB;
    const int m0  = mb * MPB;
    const int m   = m0 + tm;
    const int ju  = j0 + tg * 2;              // first of this thread's 2 units

    // ---- prologue: stage W slice into smem once ----
    for (int idx = tid; idx < KTOT * UPB; idx += NTHR) {
        int k  = idx >> 4;
        int uu = idx & 15;
        int col = j0 + uu;
        const float* Wrow = (k < H_) ? (Wh + (size_t)k * G4)
                                     : (Wx + (size_t)(k - H_) * G4);
        float2 p_if = make_float2(Wrow[0 * H_ + col], Wrow[1 * H_ + col]);
        float2 p_go = make_float2(Wrow[2 * H_ + col], Wrow[3 * H_ + col]);
        sW[(k * UPB + uu) * 2 + 0] = *(unsigned long long*)&p_if;
        sW[(k * UPB + uu) * 2 + 1] = *(unsigned long long*)&p_go;
    }
    float bi[2], bf[2], bg_[2], bo[2], c_reg[2] = {0.f, 0.f};
    #pragma unroll
    for (int q = 0; q < 2; ++q) {
        bi[q]  = bias[0 * H_ + ju + q];
        bf[q]  = bias[1 * H_ + ju + q];
        bg_[q] = bias[2 * H_ + ju + q];
        bo[q]  = bias[3 * H_ + ju + q];
    }
    __syncthreads();

    for (int t = 0; t < T_; ++t) {
        // ---- load A tile: [32 rows][h(512) | x(32)] ----
        {
            const float* hbase = out + (size_t)(t - 1) * H_;
            #pragma unroll
            for (int i = 0; i < 17; ++i) {            // 32*136/256
                int idx = i * NTHR + tid;
                int mr = idx / 136;
                int q  = idx - mr * 136;
                float4 v;
                if (q < 128) {
                    if (t == 0) v = make_float4(0.f, 0.f, 0.f, 0.f);
                    else v = *(const float4*)(hbase +
                             (size_t)(m0 + mr) * ((size_t)T_ * H_) + q * 4);
                } else {
                    v = *(const float4*)(x + (size_t)(m0 + mr) * (T_ * D_) +
                                         t * D_ + (q - 128) * 4);
                }
                float* dst = sA + mr * APITCH + q * 4;
                dst[0] = v.x; dst[1] = v.y; dst[2] = v.z; dst[3] = v.w;
            }
        }
        __syncthreads();

        // ---- z = [h,x] @ [Wh;Wx] : 1 m-row x 2 units x 4 gates ----
        unsigned long long acc00 = 0, acc01 = 0, acc10 = 0, acc11 = 0;
        const float* aptr = sA + tm * APITCH;
        const ulonglong2* wptr =
            (const ulonglong2*)(sW + (size_t)tg * 4);  // units 2tg,2tg+1

        #pragma unroll 4
        for (int k = 0; k < KTOT; ++k) {
            unsigned long long a2 = pack2(aptr[k]);
            ulonglong2 w0 = wptr[k * UPB + 0];         // unit 2tg   (if,go)
            ulonglong2 w1 = wptr[k * UPB + 1];         // unit 2tg+1 (if,go)
            ffma2(acc00, a2, w0.x); ffma2(acc01, a2, w0.y);
            ffma2(acc10, a2, w1.x); ffma2(acc11, a2, w1.y);
        }

        // ---- gates, state update, h writeback ----
        float h2[2];
        #pragma unroll
        for (int q = 0; q < 2; ++q) {
            float zi, zf, zg, zo;
            if (q == 0) { unpack2(acc00, zi, zf); unpack2(acc01, zg, zo); }
            else        { unpack2(acc10, zi, zf); unpack2(acc11, zg, zo); }
            float ig = fsig(zi + bi[q]);
            float fg = fsig(zf + bf[q]);
            float gg = ftanh(zg + bg_[q]);
            float og = fsig(zo + bo[q]);
            float cn = fg * c_reg[q] + ig * gg;
            c_reg[q] = cn;
            h2[q] = og * ftanh(cn);
        }
        *(float2*)(out + (size_t)m * ((size_t)T_ * H_) + (size_t)t * H_ + ju) =
            make_float2(h2[0], h2[1]);

        // ---- group barrier: 32 CTAs sharing this m-block ----
        __threadfence();
        __syncthreads();
        if (tid == 0) {
            unsigned prev = atomicAdd(&g_arrive[mb], 1u);
            if (prev == (unsigned)(t + 1) * 32u - 1u) {
                g_release[mb] = (unsigned)(t + 1);
            } else {
                while (g_release[mb] < (unsigned)(t + 1)) { __nanosleep(16); }
            }
        }
        __syncthreads();
    }
}

extern "C" void kernel_launch(void* const* d_in, const int* in_sizes, int n_in,
                              void* d_out, int out_size) {
    const float* x  = (const float*)d_in[0];
    const float* Wx = (const float*)d_in[1];
    const float* Wh = (const float*)d_in[2];
    const float* b  = (const float*)d_in[3];
    float* out = (float*)d_out;

    static bool attr_set = false;
    if (!attr_set) {
        cudaFuncSetAttribute(lstm_persistent,
                             cudaFuncAttributeMaxDynamicSharedMemorySize,
                             SMEM_BYTES);
        attr_set = true;
    }

    init_barrier_kernel<<<1, 32>>>();
    lstm_persistent<<<NCTA, NTHR, SMEM_BYTES>>>(x, Wx, Wh, b, out);
}